// round 2
// baseline (speedup 1.0000x reference)
#include <cuda_runtime.h>

#define HWSZ   262144
#define NIMG   128
#define AXK    26214
#define CAP    49152
#define R_HI   260
#define R_LO   560
#define NSAMP  4096

// ---------------- scratch (static device memory; no allocations) -------------
__device__ unsigned g_cand[(size_t)2 * NIMG * CAP];   // ~50 MB candidate bits
__device__ unsigned g_cand_cnt[2 * NIMG];
__device__ unsigned g_above[2 * NIMG];
__device__ unsigned g_hi[2 * NIMG];
__device__ unsigned g_lo[2 * NIMG];
__device__ unsigned g_thr[2 * NIMG];
__device__ double   g_acc;

// Bit-identical Roberts magnitude everywhere (fixed fmaf order, IEEE sqrtf).
// q points at element p of a 512x512 image; i=p>>9, j=p&511.
__device__ __forceinline__ float edge_mag(const float* __restrict__ q, int i, int j) {
    float a = __ldg(q);
    float b = (j < 511) ? __ldg(q + 1)   : 0.0f;
    float c = (i < 511) ? __ldg(q + 512) : 0.0f;
    float d = (i < 511 && j < 511) ? __ldg(q + 513) : 0.0f;
    float gx = a - d;
    float gy = b - c;
    return sqrtf(fmaf(gx, gx, fmaf(gy, gy, 1e-12f)));
}

__device__ __forceinline__ unsigned blockReduceSum256(unsigned val, unsigned* sred) {
    __syncthreads();                       // protect sred reuse
    #pragma unroll
    for (int off = 16; off; off >>= 1) val += __shfl_down_sync(0xffffffffu, val, off);
    if ((threadIdx.x & 31) == 0) sred[threadIdx.x >> 5] = val;
    __syncthreads();
    if (threadIdx.x == 0) {
        unsigned t = 0;
        #pragma unroll
        for (int w = 0; w < 8; w++) t += sred[w];
        sred[8] = t;
    }
    __syncthreads();
    return sred[8];
}

// ---------------- K0: zero counters ------------------------------------------
__global__ void k_zero() {
    int t = threadIdx.x;
    if (t < 2 * NIMG) { g_cand_cnt[t] = 0; g_above[t] = 0; }
    if (t == 0) g_acc = 0.0;
}

// ---------------- K1: sampled bracket [lo, hi] per (image, tensor) -----------
__global__ void k_bracket(const float* __restrict__ tgt, const float* __restrict__ prd) {
    __shared__ unsigned sh[NSAMP];
    __shared__ unsigned sred[16];
    int n = blockIdx.x, sel = blockIdx.y;
    const float* img = (sel ? prd : tgt) + (size_t)n * HWSZ;
    int tid = threadIdx.x;

    // 128 chunks of 32 consecutive pixels, spread over the image (coalesced).
    #pragma unroll
    for (int k = 0; k < 16; k++) {
        int s = k * 256 + tid;
        int chunk = s >> 5, off = s & 31;
        int p = chunk * 2048 + ((chunk * 11) & 63) * 32 + off;
        int i = p >> 9, j = p & 511;
        sh[s] = __float_as_uint(edge_mag(img + p, i, j));
    }
    __syncthreads();

    unsigned results[2];
    int ranks[2] = { R_HI, R_LO };
    for (int r = 0; r < 2; r++) {
        unsigned prefix = 0;
        long rank = ranks[r];
        for (int bit = 31; bit >= 0; bit--) {
            unsigned want = (prefix | (1u << bit)) >> bit;
            unsigned cnt = 0;
            #pragma unroll
            for (int k = 0; k < 16; k++)
                cnt += ((sh[k * 256 + tid] >> bit) == want);
            unsigned total = blockReduceSum256(cnt, sred);
            if ((long)total >= rank) prefix |= (1u << bit);
            else                     rank  -= (long)total;
        }
        results[r] = prefix;
    }
    if (tid == 0) {
        int ns = sel * NIMG + n;
        g_hi[ns] = results[0];   // sample rank 260 (above 10% quantile whp)
        g_lo[ns] = results[1];   // sample rank 560 (below 10% quantile whp)
    }
}

// ---------------- K2: count above hi + compact (lo, hi] candidates -----------
__global__ void k_count_compact(const float* __restrict__ tgt, const float* __restrict__ prd) {
    __shared__ unsigned sred[16];
    int n = blockIdx.y, sel = blockIdx.z;
    int ns = sel * NIMG + n;
    const float* img = (sel ? prd : tgt) + (size_t)n * HWSZ;
    unsigned hi = g_hi[ns], lo = g_lo[ns];
    int tid = threadIdx.x, lane = tid & 31;
    int base = blockIdx.x * 32768;
    unsigned above = 0;

    for (int k = 0; k < 128; k++) {
        int p = base + k * 256 + tid;
        int i = p >> 9, j = p & 511;
        unsigned v = __float_as_uint(edge_mag(img + p, i, j));
        above += (v > hi);
        bool want = (v > lo) && (v <= hi);
        unsigned bal = __ballot_sync(0xffffffffu, want);
        if (bal) {
            int leader = __ffs(bal) - 1;
            unsigned basei = 0;
            if (lane == leader) basei = atomicAdd(&g_cand_cnt[ns], (unsigned)__popc(bal));
            basei = __shfl_sync(0xffffffffu, basei, leader);
            if (want) {
                unsigned idx = basei + __popc(bal & ((1u << lane) - 1u));
                if (idx < CAP) g_cand[(size_t)ns * CAP + idx] = v;
            }
        }
    }
    unsigned tot = blockReduceSum256(above, sred);
    if (tid == 0) atomicAdd(&g_above[ns], tot);
}

// ---------------- K3: exact j-th largest among candidates (digit narrowing) --
__global__ void k_select() {
    __shared__ unsigned hcnt[256];
    __shared__ unsigned ssuf[256];
    __shared__ unsigned s_lo, s_hi, s_B;
    __shared__ long     s_j;
    __shared__ int      s_done;

    int ns = blockIdx.x;
    int tid = threadIdx.x;
    unsigned m = g_cand_cnt[ns]; if (m > CAP) m = CAP;
    unsigned above = g_above[ns];
    long j = (long)AXK - (long)above;
    unsigned lo0 = g_lo[ns] + 1u, hi0 = g_hi[ns];

    if (tid == 0) {
        if (j <= 0)                    { g_thr[ns] = g_hi[ns] + 1u; s_done = 1; }
        else if ((unsigned long)j > m) { g_thr[ns] = lo0;           s_done = 1; }
        else { s_lo = lo0; s_hi = hi0; s_j = j; s_done = 0; }
    }
    __syncthreads();
    if (s_done) return;

    while (true) {
        unsigned cur_lo = s_lo, cur_hi = s_hi;
        long jj = s_j;
        if (cur_lo >= cur_hi) break;
        unsigned long long width = (unsigned long long)cur_hi - cur_lo + 1ull;

        hcnt[tid] = 0;
        __syncthreads();
        for (unsigned idx = tid; idx < m; idx += 256) {
            unsigned v = g_cand[(size_t)ns * CAP + idx];
            if (v >= cur_lo && v <= cur_hi) {
                unsigned b = (unsigned)((((unsigned long long)(v - cur_lo)) << 8) / width);
                atomicAdd(&hcnt[b], 1u);
            }
        }
        __syncthreads();

        // suffix sums (Hillis–Steele)
        ssuf[tid] = hcnt[tid];
        __syncthreads();
        for (int off = 1; off < 256; off <<= 1) {
            unsigned add = (tid + off < 256) ? ssuf[tid + off] : 0u;
            __syncthreads();
            ssuf[tid] += add;
            __syncthreads();
        }
        if (ssuf[0] < (unsigned long)jj) {   // lost candidates (cap overflow) fallback
            if (tid == 0) g_thr[ns] = cur_lo;
            return;
        }
        unsigned sufB  = ssuf[tid];
        unsigned sufB1 = (tid < 255) ? ssuf[tid + 1] : 0u;
        if ((long)sufB >= jj && (long)sufB1 < jj) s_B = (unsigned)tid;
        __syncthreads();
        unsigned B = s_B;
        long j_new = jj - (long)((B < 255) ? ssuf[B + 1] : 0u);
        unsigned new_lo = cur_lo + (unsigned)(((unsigned long long)B * width + 255ull) >> 8);
        unsigned new_hi = cur_lo + (unsigned)((((unsigned long long)(B + 1) * width + 255ull) >> 8) - 1ull);
        __syncthreads();
        if (tid == 0) { s_lo = new_lo; s_hi = new_hi; s_j = j_new; }
        __syncthreads();
    }
    if (tid == 0) g_thr[ns] = s_lo;
}

// ---------------- K4: fused per-pixel scatter-scan + reduction ---------------
__global__ void k_scan(const float* __restrict__ tgt, const float* __restrict__ prd) {
    __shared__ unsigned shT[NIMG];
    __shared__ unsigned shP[NIMG];
    __shared__ float fred[8];
    int tid = threadIdx.x;
    if (tid < NIMG) shT[tid] = g_thr[tid];
    else            shP[tid - NIMG] = g_thr[tid];
    __syncthreads();

    int p = blockIdx.x * 256 + tid;
    int i = p >> 9, j = p & 511;
    const float* tp = tgt + p;
    const float* pp = prd + p;
    float etf = 0.0f, epf = 0.0f, acc = 0.0f;

    #pragma unroll 4
    for (int n = 0; n < NIMG; n++) {
        float et = edge_mag(tp, i, j);
        float ep = edge_mag(pp, i, j);
        if (__float_as_uint(et) >= shT[n]) etf = et;
        if (__float_as_uint(ep) >= shP[n]) epf = ep;
        acc += __fdividef(fabsf(etf - epf), etf + epf + 1e-5f);
        tp += HWSZ; pp += HWSZ;
    }

    #pragma unroll
    for (int off = 16; off; off >>= 1) acc += __shfl_down_sync(0xffffffffu, acc, off);
    if ((tid & 31) == 0) fred[tid >> 5] = acc;
    __syncthreads();
    if (tid == 0) {
        float t = 0.0f;
        #pragma unroll
        for (int w = 0; w < 8; w++) t += fred[w];
        atomicAdd(&g_acc, (double)t);
    }
}

// ---------------- K5: finalize ------------------------------------------------
__global__ void k_final(const float* __restrict__ alpha, float* __restrict__ out) {
    out[0] = (float)((double)alpha[0] * g_acc / 33554432.0);
}

extern "C" void kernel_launch(void* const* d_in, const int* in_sizes, int n_in,
                              void* d_out, int out_size) {
    const float* pred  = (const float*)d_in[0];
    const float* tgt   = (const float*)d_in[1];
    const float* alpha = (const float*)d_in[2];
    float* out = (float*)d_out;

    k_zero<<<1, 256>>>();
    k_bracket<<<dim3(NIMG, 2), 256>>>(tgt, pred);
    k_count_compact<<<dim3(8, NIMG, 2), 256>>>(tgt, pred);
    k_select<<<2 * NIMG, 256>>>();
    k_scan<<<HWSZ / 256, 256>>>(tgt, pred);
    k_final<<<1, 1>>>(alpha, out);
}

// round 3
// speedup vs baseline: 2.6666x; 2.6666x over previous
#include <cuda_runtime.h>

#define HWSZ   262144
#define NIMG   128
#define AXK    26214
#define SEG    16
#define CAPB   4096
#define CAPI   (SEG*CAPB)
#define R_HI   260
#define R_LO   560

// ---------------- static scratch ----------------
__device__ unsigned g_cand[(size_t)2 * NIMG * CAPI];   // 64 MB
__device__ unsigned g_cnt[2 * NIMG][SEG];
__device__ unsigned g_above[2 * NIMG];
__device__ unsigned g_hi[2 * NIMG], g_lo[2 * NIMG], g_thr[2 * NIMG];
__device__ double   g_acc;

// Bit-identical squared Roberts magnitude everywhere (fixed op order).
__device__ __forceinline__ float m2_one(float a, float b, float c, float d) {
    float gx = a - d, gy = b - c;
    return fmaf(gx, gx, fmaf(gy, gy, 1e-12f));
}

struct Quad { float4 v0, v1; float x4, y4; };

// Load a 4-pixel quad at p (quad-aligned, warp covers 128 contiguous px in one row).
__device__ __forceinline__ Quad load_quad(const float* __restrict__ img, int p, int lane) {
    Quad q;
    int i = p >> 9, j = p & 511;
    q.v0 = __ldg((const float4*)(img + p));
    bool lastrow = (i == 511);
    q.v1 = lastrow ? make_float4(0.f, 0.f, 0.f, 0.f)
                   : __ldg((const float4*)(img + p + 512));
    q.x4 = __shfl_down_sync(0xffffffffu, q.v0.x, 1);
    q.y4 = __shfl_down_sync(0xffffffffu, q.v1.x, 1);
    if (lane == 31) {
        bool hn = (j + 4) < 512;
        q.x4 = hn ? __ldg(img + p + 4) : 0.0f;
        q.y4 = (hn && !lastrow) ? __ldg(img + p + 516) : 0.0f;
    }
    return q;
}

__device__ __forceinline__ void quad_m2(const Quad& q, float m2[4]) {
    m2[0] = m2_one(q.v0.x, q.v0.y, q.v1.x, q.v1.y);
    m2[1] = m2_one(q.v0.y, q.v0.z, q.v1.y, q.v1.z);
    m2[2] = m2_one(q.v0.z, q.v0.w, q.v1.z, q.v1.w);
    m2[3] = m2_one(q.v0.w, q.x4,   q.v1.w, q.y4);
}

// inclusive suffix sum over 256 shared entries (256 threads); caller syncs before.
__device__ __forceinline__ void suffix256(volatile unsigned* s, int tid) {
    #pragma unroll
    for (int off = 1; off < 256; off <<= 1) {
        unsigned add = (tid + off < 256) ? s[tid + off] : 0u;
        __syncthreads();
        s[tid] += add;
        __syncthreads();
    }
}

// ---------------- K0: zero ----------------
__global__ void k_zero() {
    int t = blockIdx.x * 256 + threadIdx.x;
    if (t < 2 * NIMG * SEG) ((unsigned*)g_cnt)[t] = 0;
    if (t < 2 * NIMG) g_above[t] = 0;
    if (t == 0) g_acc = 0.0;
}

// ---------------- K1: sampled bracket via 4-round radix on 4096 samples ------
__global__ void k_bracket(const float* __restrict__ tgt, const float* __restrict__ prd) {
    __shared__ unsigned sval[4096];
    __shared__ unsigned hist[256];
    __shared__ unsigned s_d;
    int n = blockIdx.x, sel = blockIdx.y;
    const float* img = (sel ? prd : tgt) + (size_t)n * HWSZ;
    int tid = threadIdx.x, lane = tid & 31, wid = tid >> 5;

    #pragma unroll
    for (int k = 0; k < 4; k++) {
        int c   = k * 8 + wid;                 // 32 chunks of 128 px
        int row = (c * 509) & 511;             // distinct rows
        int col = (c & 3) * 128;
        int p   = row * 512 + col + lane * 4;
        Quad q = load_quad(img, p, lane);
        float m2[4]; quad_m2(q, m2);
        int s = c * 128 + lane * 4;
        sval[s + 0] = __float_as_uint(m2[0]);
        sval[s + 1] = __float_as_uint(m2[1]);
        sval[s + 2] = __float_as_uint(m2[2]);
        sval[s + 3] = __float_as_uint(m2[3]);
    }
    __syncthreads();

    unsigned res[2]; const int ranks[2] = { R_HI, R_LO };
    for (int r = 0; r < 2; r++) {
        unsigned prefix = 0, rank = (unsigned)ranks[r];
        for (int shift = 24; shift >= 0; shift -= 8) {
            hist[tid] = 0;
            __syncthreads();
            unsigned hmask = (shift == 24) ? 0u : (0xFFFFFFFFu << (shift + 8));
            #pragma unroll
            for (int k = 0; k < 16; k++) {
                unsigned v = sval[k * 256 + tid];
                if ((v & hmask) == prefix) atomicAdd(&hist[(v >> shift) & 255u], 1u);
            }
            __syncthreads();
            suffix256(hist, tid);
            unsigned sufd  = hist[tid];
            unsigned sufd1 = (tid < 255) ? hist[tid + 1] : 0u;
            if (sufd >= rank && sufd1 < rank) s_d = (unsigned)tid;
            __syncthreads();
            unsigned d = s_d;
            rank -= (d < 255) ? hist[d + 1] : 0u;
            prefix |= d << shift;
            __syncthreads();
        }
        res[r] = prefix;
    }
    if (tid == 0) {
        int ns = sel * NIMG + n;
        g_hi[ns] = res[0];   // sample rank 260 (above 10% quantile whp)
        g_lo[ns] = res[1];   // sample rank 560 (below 10% quantile whp)
    }
}

// ---------------- K2: count above-hi + per-segment compaction ----------------
__global__ void __launch_bounds__(256) k_count(const float* __restrict__ tgt,
                                               const float* __restrict__ prd) {
    __shared__ unsigned scnt;
    __shared__ unsigned sred[8];
    int seg = blockIdx.x, n = blockIdx.y, sel = blockIdx.z;
    int ns = sel * NIMG + n;
    const float* img = (sel ? prd : tgt) + (size_t)n * HWSZ;
    unsigned hi = g_hi[ns], lo = g_lo[ns];
    int tid = threadIdx.x, lane = tid & 31;
    if (tid == 0) scnt = 0;
    __syncthreads();
    unsigned* seg_out = g_cand + (size_t)ns * CAPI + (size_t)seg * CAPB;
    unsigned above = 0;
    int base = seg * (HWSZ / SEG);

    #pragma unroll 2
    for (int it = 0; it < (HWSZ / SEG) / 1024; it++) {   // 16 iters
        int p = base + it * 1024 + tid * 4;
        Quad q = load_quad(img, p, lane);
        float m2[4]; quad_m2(q, m2);
        unsigned vb[4], c = 0; bool isc[4];
        #pragma unroll
        for (int k = 0; k < 4; k++) {
            vb[k] = __float_as_uint(m2[k]);
            above += (vb[k] > hi);
            isc[k] = (vb[k] > lo) && (vb[k] <= hi);
            c += isc[k];
        }
        unsigned inc = c;
        #pragma unroll
        for (int o = 1; o < 32; o <<= 1) {
            unsigned t = __shfl_up_sync(0xffffffffu, inc, o);
            if (lane >= o) inc += t;
        }
        unsigned tot = __shfl_sync(0xffffffffu, inc, 31);
        if (tot) {
            unsigned bb = 0;
            if (lane == 31) bb = atomicAdd(&scnt, tot);
            bb = __shfl_sync(0xffffffffu, bb, 31);
            unsigned off = bb + inc - c;
            #pragma unroll
            for (int k = 0; k < 4; k++)
                if (isc[k]) { if (off < CAPB) seg_out[off] = vb[k]; off++; }
        }
    }
    #pragma unroll
    for (int o = 16; o; o >>= 1) above += __shfl_down_sync(0xffffffffu, above, o);
    if (lane == 0) sred[tid >> 5] = above;
    __syncthreads();
    if (tid == 0) {
        unsigned t = 0;
        #pragma unroll
        for (int w = 0; w < 8; w++) t += sred[w];
        atomicAdd(&g_above[ns], t);
        g_cnt[ns][seg] = min(scnt, (unsigned)CAPB);
    }
}

// ---------------- K3: exact j-th largest, fixed 4-round base-256 radix -------
__global__ void k_select() {
    __shared__ unsigned hist[256];
    __shared__ unsigned s_d;
    __shared__ unsigned cnts[SEG];
    int ns = blockIdx.x, tid = threadIdx.x;
    if (tid < SEG) cnts[tid] = min(g_cnt[ns][tid], (unsigned)CAPB);
    __syncthreads();
    unsigned above = g_above[ns];
    long j = (long)AXK - (long)above;
    unsigned m = 0;
    for (int s = 0; s < SEG; s++) m += cnts[s];
    if (j <= 0)              { if (tid == 0) g_thr[ns] = g_hi[ns] + 1u; return; }
    if ((unsigned long)j > m){ if (tid == 0) g_thr[ns] = g_lo[ns] + 1u; return; }
    const unsigned* cand = g_cand + (size_t)ns * CAPI;

    unsigned prefix = 0, rank = (unsigned)j;
    for (int shift = 24; shift >= 0; shift -= 8) {
        hist[tid] = 0;
        __syncthreads();
        unsigned hmask = (shift == 24) ? 0u : (0xFFFFFFFFu << (shift + 8));
        for (int s = 0; s < SEG; s++) {
            unsigned cnt = cnts[s];
            const unsigned* segp = cand + s * CAPB;
            for (unsigned idx = tid; idx < cnt; idx += 256) {
                unsigned v = segp[idx];
                if ((v & hmask) == prefix) atomicAdd(&hist[(v >> shift) & 255u], 1u);
            }
        }
        __syncthreads();
        suffix256(hist, tid);
        unsigned sufd  = hist[tid];
        unsigned sufd1 = (tid < 255) ? hist[tid + 1] : 0u;
        if (sufd >= rank && sufd1 < rank) s_d = (unsigned)tid;
        __syncthreads();
        unsigned d = s_d;
        rank -= (d < 255) ? hist[d + 1] : 0u;
        prefix |= d << shift;
        __syncthreads();
    }
    if (tid == 0) g_thr[ns] = prefix;   // exact AXK-th largest m2 bits
}

// ---------------- K4: fused per-pixel scatter-scan + reduction ---------------
__global__ void __launch_bounds__(256) k_scan(const float* __restrict__ tgt,
                                              const float* __restrict__ prd) {
    __shared__ unsigned shT[NIMG], shP[NIMG];
    __shared__ float fred[8];
    int tid = threadIdx.x, lane = tid & 31;
    if (tid < NIMG) shT[tid] = g_thr[tid];
    else            shP[tid - NIMG] = g_thr[tid];
    __syncthreads();

    int p = (blockIdx.x * 256 + tid) * 4;
    float etf[4] = {0.f,0.f,0.f,0.f}, epf[4] = {0.f,0.f,0.f,0.f};
    float acc = 0.0f;

    #pragma unroll 2
    for (int n = 0; n < NIMG; n++) {
        Quad qt = load_quad(tgt + (size_t)n * HWSZ, p, lane);
        Quad qp = load_quad(prd + (size_t)n * HWSZ, p, lane);
        float mt[4], mp[4];
        quad_m2(qt, mt); quad_m2(qp, mp);
        unsigned thT = shT[n], thP = shP[n];
        #pragma unroll
        for (int k = 0; k < 4; k++) {
            if (__float_as_uint(mt[k]) >= thT) etf[k] = sqrtf(mt[k]);
            if (__float_as_uint(mp[k]) >= thP) epf[k] = sqrtf(mp[k]);
            acc += __fdividef(fabsf(etf[k] - epf[k]), etf[k] + epf[k] + 1e-5f);
        }
    }

    #pragma unroll
    for (int o = 16; o; o >>= 1) acc += __shfl_down_sync(0xffffffffu, acc, o);
    if (lane == 0) fred[tid >> 5] = acc;
    __syncthreads();
    if (tid == 0) {
        float t = 0.0f;
        #pragma unroll
        for (int w = 0; w < 8; w++) t += fred[w];
        atomicAdd(&g_acc, (double)t);
    }
}

// ---------------- K5: finalize ----------------
__global__ void k_final(const float* __restrict__ alpha, float* __restrict__ out) {
    out[0] = (float)((double)alpha[0] * g_acc / 33554432.0);
}

extern "C" void kernel_launch(void* const* d_in, const int* in_sizes, int n_in,
                              void* d_out, int out_size) {
    const float* pred  = (const float*)d_in[0];
    const float* tgt   = (const float*)d_in[1];
    const float* alpha = (const float*)d_in[2];
    float* out = (float*)d_out;

    k_zero<<<16, 256>>>();
    k_bracket<<<dim3(NIMG, 2), 256>>>(tgt, pred);
    k_count<<<dim3(SEG, NIMG, 2), 256>>>(tgt, pred);
    k_select<<<2 * NIMG, 256>>>();
    k_scan<<<HWSZ / 1024, 256>>>(tgt, pred);
    k_final<<<1, 1>>>(alpha, out);
}